// round 16
// baseline (speedup 1.0000x reference)
#include <cuda_runtime.h>

// Problem constants
#define NN 4
#define CC 256
#define HW 20480            // 128*160
#define PP (NN*HW)          // 81920 pixels
#define NB 64               // depth bins
#define CHUNK 10240         // pixels per block chunk
#define NCHUNKS (PP/CHUNK)  // 8
#define K1_BLOCKS 80

// Scratch (no device allocation allowed -> __device__ globals)
__device__ unsigned char g_idx[PP];
__device__ float g_sums[2*NB*CC];        // [tensor][bin][channel]

// ---------------------------------------------------------------------------
// K1: bin index per pixel (uint8) + zero g_sums and out.
// (Counts are NOT needed anywhere: 1/count cancels inside the L2-normalize,
//  so the histogram/atomics from earlier rounds are gone.)
__device__ __forceinline__ unsigned char bin_of(float d) {
    float t = d * 64.0f;                       // bin_size = 1/64 exactly
    if (t >= 0.0f && t < 64.0f) return (unsigned char)(int)t;  // trunc == ref
    return (unsigned char)64;                  // overflow/invalid bin
}

__global__ void __launch_bounds__(256) k1_idx(const float* __restrict__ depth,
                                              float* __restrict__ out) {
    const int g = blockIdx.x * 256 + threadIdx.x;  // 80*256 = 20480 float4s
    float4 d = ((const float4*)depth)[g];
    uchar4 b4;
    b4.x = bin_of(d.x); b4.y = bin_of(d.y); b4.z = bin_of(d.z); b4.w = bin_of(d.w);
    ((uchar4*)g_idx)[g] = b4;

    // zero scratch consumed by later kernels
    for (int i = g; i < 2*NB*CC; i += K1_BLOCKS*256) g_sums[i] = 0.f;
    if (g == 0) out[0] = 0.f;
}

// ---------------------------------------------------------------------------
// K2: streaming segment-sum, both tensors in one grid (EXACT R6 body — the
// measured-good ~48us configuration; kept byte-identical for attribution).
// Block = 128 threads = 4 warps = 4 channels; warp lanes stream pixels.
// grid = (chunk 0..7, cgroup 0..63, tensor 0..1) -> 1024 blocks, 32KB smem,
// 7 blocks/SM (capacity 1036) -> one full wave at 43% occ.
// Private smem accumulator column per thread: acc[bin][tid] (bank = tid%32,
// conflict-free, race-free RMW, no atomics in the hot loop).
__global__ void __launch_bounds__(128) k2_accum(const float* __restrict__ S,
                                                const float* __restrict__ T) {
    extern __shared__ float acc[];             // [NB][128] = 32 KB
    const int tid  = threadIdx.x;
    const int warp = tid >> 5;
    const int lane = tid & 31;
    const int chunk = blockIdx.x;              // 0..7
    const int n   = chunk >> 1;
    const int hw0 = (chunk & 1) * CHUNK;
    const int c   = blockIdx.y * 4 + warp;     // this warp's channel

    const unsigned char* __restrict__ ib = g_idx + n*HW + hw0;
    const float* __restrict__ src =
        (blockIdx.z ? T : S) + ((long)(n*CC + c))*HW + hw0;

    for (int i = tid; i < NB*128; i += 128) acc[i] = 0.f;
    __syncthreads();

    #pragma unroll 2
    for (int it = 0; it < CHUNK/256; ++it) {   // 40 iters, 8 px/lane/iter
        const int p = it*256 + lane*4;
        float4 v0 = *(const float4*)(src + p);
        float4 v1 = *(const float4*)(src + p + 128);
        uchar4 b0 = *(const uchar4*)(ib + p);
        uchar4 b1 = *(const uchar4*)(ib + p + 128);
        if (b0.x < 64) acc[(int)b0.x*128 + tid] += v0.x;
        if (b0.y < 64) acc[(int)b0.y*128 + tid] += v0.y;
        if (b0.z < 64) acc[(int)b0.z*128 + tid] += v0.z;
        if (b0.w < 64) acc[(int)b0.w*128 + tid] += v0.w;
        if (b1.x < 64) acc[(int)b1.x*128 + tid] += v1.x;
        if (b1.y < 64) acc[(int)b1.y*128 + tid] += v1.y;
        if (b1.z < 64) acc[(int)b1.z*128 + tid] += v1.z;
        if (b1.w < 64) acc[(int)b1.w*128 + tid] += v1.w;
    }
    __syncthreads();

    // Tail reduce: lane l sums bins l and l+32 across this warp's 32 columns.
    // Rotation (j+lane)&31 keeps all lanes on distinct banks every step.
    const float* aw = acc + warp*32;
    float s0 = 0.f, s1 = 0.f;
    #pragma unroll
    for (int j = 0; j < 32; ++j) {
        const int col = (j + lane) & 31;
        s0 += aw[lane*128 + col];
        s1 += aw[(lane + 32)*128 + col];
    }
    float* dst = g_sums + blockIdx.z*NB*CC + c;
    atomicAdd(dst + lane*CC,        s0);
    atomicAdd(dst + (lane + 32)*CC, s1);
}

// ---------------------------------------------------------------------------
// K3: loss directly from RAW sums (no counts, no normalize pass, no smem
// proto mirror). sim[i][j] = dot(s_i,s_j)/(max(|s_i|,eps)*max(|s_j|,eps)):
// the 1/count factors cancel inside F.normalize; empty bins (s=0) give
// sim=0 exactly as the reference's eps guard does.
// 64 blocks x 256 threads; row i register-cached, rows j streamed from L2
// (64 x 128KB = 8MB L2 traffic). Norms from self-dots on the fly.
__global__ void __launch_bounds__(256) k3_loss(float* __restrict__ out) {
    const int i = blockIdx.x;
    const int tid = threadIdx.x, warp = tid >> 5, lane = tid & 31;

    const float* __restrict__ Si = g_sums + i*CC;
    const float* __restrict__ Ti = g_sums + (NB + i)*CC;
    float pS[8], pT[8];
    #pragma unroll
    for (int k = 0; k < 8; ++k) {
        pS[k] = Si[lane + 32*k];
        pT[k] = Ti[lane + 32*k];
    }
    // self-dots of row i -> inverse norms
    float dSii = 0.f, dTii = 0.f;
    #pragma unroll
    for (int k = 0; k < 8; ++k) { dSii += pS[k]*pS[k]; dTii += pT[k]*pT[k]; }
    #pragma unroll
    for (int o = 16; o; o >>= 1) {
        dSii += __shfl_xor_sync(0xffffffffu, dSii, o);
        dTii += __shfl_xor_sync(0xffffffffu, dTii, o);
    }
    const float invSi = 1.0f / fmaxf(sqrtf(dSii), 1e-12f);
    const float invTi = 1.0f / fmaxf(sqrtf(dTii), 1e-12f);

    float accv = 0.f;
    for (int j = warp; j < NB; j += 8) {
        const float* __restrict__ qSp = g_sums + j*CC;
        const float* __restrict__ qTp = g_sums + (NB + j)*CC;
        float qS[8], qT[8];
        #pragma unroll
        for (int k = 0; k < 8; ++k) {
            qS[k] = qSp[lane + 32*k];
            qT[k] = qTp[lane + 32*k];
        }
        float sS = 0.f, sT = 0.f, nS = 0.f, nT = 0.f;
        #pragma unroll
        for (int k = 0; k < 8; ++k) {
            sS += pS[k]*qS[k]; nS += qS[k]*qS[k];
            sT += pT[k]*qT[k]; nT += qT[k]*qT[k];
        }
        #pragma unroll
        for (int o = 16; o; o >>= 1) {
            sS += __shfl_xor_sync(0xffffffffu, sS, o);
            nS += __shfl_xor_sync(0xffffffffu, nS, o);
            sT += __shfl_xor_sync(0xffffffffu, sT, o);
            nT += __shfl_xor_sync(0xffffffffu, nT, o);
        }
        const float simS = sS * invSi / fmaxf(sqrtf(nS), 1e-12f);
        const float simT = sT * invTi / fmaxf(sqrtf(nT), 1e-12f);
        const float d = simS - simT;
        accv += d * d;                          // identical on all lanes
    }
    if (lane == 0) atomicAdd(out, accv * (1.0f/(NB*NB)));
}

// ---------------------------------------------------------------------------
extern "C" void kernel_launch(void* const* d_in, const int* in_sizes, int n_in,
                              void* d_out, int out_size) {
    (void)in_sizes; (void)n_in; (void)out_size;
    const float* S     = (const float*)d_in[0];
    const float* T     = (const float*)d_in[1];
    const float* depth = (const float*)d_in[2];
    float* out = (float*)d_out;

    k1_idx  <<<K1_BLOCKS, 256>>>(depth, out);
    k2_accum<<<dim3(NCHUNKS, CC/4, 2), 128, NB*128*sizeof(float)>>>(S, T);
    k3_loss <<<NB, 256>>>(out);
}